// round 12
// baseline (speedup 1.0000x reference)
#include <cuda_runtime.h>
#include <math.h>
#include <stdint.h>

#define ED   1024
#define GH   1024
#define NLAY 3
#define NHEAD 8
#define HDIM 128
#define NNODE 2048
#define BB   1024
#define TEMPR 0.05f
#define LAPW 0.1f

#if (defined(__CUDA_ARCH_FEAT_SM103_ALL) || defined(__CUDA_ARCH_FEAT_SM100_ALL) || \
     (defined(__CUDA_ARCH_SPECIFIC__) && defined(__CUDA_ARCH__) && __CUDA_ARCH__ >= 1000))
#define HAVE_TCGEN05 1
#else
#define HAVE_TCGEN05 0
#endif

// ---------------- scratch (device globals; no allocation allowed) ----------------
__device__ float g_x[NNODE * GH];
__device__ float g_xr[NNODE * GH];
__device__ float g_Wh[NNODE * GH];
__device__ float g_Wcat[GH * ED];
__device__ float g_wT[ED * GH];
__device__ float g_lapr[NNODE * NNODE];
__device__ float g_geT[ED * NNODE];
__device__ float g_s1[NHEAD * NNODE];
__device__ float g_s2[NHEAD * NNODE];
__device__ float g_hb[NNODE * GH];
__device__ int   g_cnt[NNODE];
__device__ int   g_off[NNODE + 1];
__device__ int   g_cols[NNODE * 256];
__device__ float g_ge[NNODE * ED];
__device__ float g_t[NNODE * ED];
__device__ float g_tmp1[BB * ED];
__device__ float g_tmp2[BB * ED];
__device__ float g_q[BB * ED];
__device__ float g_p[BB * ED];
__device__ float g_neg[BB * BB];
__device__ float g_rowv[BB];
__device__ float g_part[256];
__device__ float g_scal[2];

// ---------------- small PTX helpers ----------------------------------------------
__device__ __forceinline__ float tf32r(float x)
{
    float y;
    asm("cvt.rna.tf32.f32 %0, %1;" : "=f"(y) : "f"(x));
    return y;
}

__device__ __forceinline__ void cpasync16(uint32_t dst, const void* src)
{
    asm volatile("cp.async.cg.shared.global [%0], [%1], 16;\n" :: "r"(dst), "l"(src));
}

__device__ __forceinline__ uint32_t elect_one_pred() {
    uint32_t pred;
    asm volatile(
        "{\n\t.reg .pred p;\n\telect.sync _|p, 0xFFFFFFFF;\n\tselp.b32 %0, 1, 0, p;\n\t}"
        : "=r"(pred));
    return pred;
}

// legacy tensor-core mma (works on ALL sm_80+ targets, incl. plain sm_103)
__device__ __forceinline__ void mma_tf32_frag(float* d, const float* a, const float* b)
{
    asm volatile(
        "mma.sync.aligned.m16n8k8.row.col.f32.tf32.tf32.f32 "
        "{%0,%1,%2,%3}, {%4,%5,%6,%7}, {%8,%9}, {%0,%1,%2,%3};\n"
        : "+f"(d[0]), "+f"(d[1]), "+f"(d[2]), "+f"(d[3])
        : "r"(__float_as_uint(a[0])), "r"(__float_as_uint(a[1])),
          "r"(__float_as_uint(a[2])), "r"(__float_as_uint(a[3])),
          "r"(__float_as_uint(b[0])), "r"(__float_as_uint(b[1])));
}

#define MBARRIER_INIT(addr, count) \
    asm volatile("mbarrier.init.shared.b64 [%0], %1;" :: "r"((uint32_t)(addr)), "r"((uint32_t)(count)) : "memory")

#define MBARRIER_WAIT_PARITY(mbar_smem_addr, phase_parity) do { \
    uint32_t _mbar = (uint32_t)(mbar_smem_addr); \
    uint32_t _parity = (uint32_t)(phase_parity); \
    uint32_t _done; \
    asm volatile( \
        "{\n\t.reg .pred p;\n\t" \
        "mbarrier.try_wait.parity.acquire.cta.shared::cta.b64 p, [%1], %2;\n\t" \
        "selp.b32 %0, 1, 0, p;\n\t}" \
        : "=r"(_done) : "r"(_mbar), "r"(_parity) : "memory"); \
    if (!_done) { \
        asm volatile( \
            "{\n\t.reg .pred P1;\n\t" \
            "WAIT_LOOP_%=:\n\t" \
            "mbarrier.try_wait.parity.acquire.cta.shared::cta.b64 P1, [%0], %1, 0x989680;\n\t" \
            "@P1 bra.uni WAIT_DONE_%=;\n\t" \
            "bra.uni WAIT_LOOP_%=;\n\t" \
            "WAIT_DONE_%=:\n\t}" \
            :: "r"(_mbar), "r"(_parity) : "memory"); \
    } \
} while(0)

#if HAVE_TCGEN05
#define TCGEN05_ALLOC(smem_result_addr, nCols) \
    asm volatile("tcgen05.alloc.cta_group::1.sync.aligned.shared::cta.b32 [%0], %1;" \
        :: "r"((uint32_t)(smem_result_addr)), "r"((uint32_t)(nCols)) : "memory")

#define TCGEN05_DEALLOC(tmem_addr, nCols) \
    asm volatile("tcgen05.dealloc.cta_group::1.sync.aligned.b32 %0, %1;" \
        :: "r"(tmem_addr), "r"(nCols))

#define TCGEN05_COMMIT(mbar_smem_addr) \
    asm volatile("tcgen05.commit.cta_group::1.mbarrier::arrive::one.shared::cluster.b64 [%0];" \
        :: "r"((uint32_t)(mbar_smem_addr)) : "memory")

#define TCGEN05_FENCE_AFTER() \
    asm volatile("tcgen05.fence::after_thread_sync;" ::: "memory")

#define TCGEN05_FENCE_BEFORE() \
    asm volatile("tcgen05.fence::before_thread_sync;" ::: "memory")

#define TCGEN05_WAIT_LD() \
    asm volatile("tcgen05.wait::ld.sync.aligned;" ::: "memory")

#define TCGEN05_LD_32X32B_X32(r, tmem_addr) \
    asm volatile( \
        "tcgen05.ld.sync.aligned.32x32b.x32.b32 " \
        "{%0, %1, %2, %3, %4, %5, %6, %7, " \
        " %8, %9, %10, %11, %12, %13, %14, %15, " \
        " %16, %17, %18, %19, %20, %21, %22, %23, " \
        " %24, %25, %26, %27, %28, %29, %30, %31}, [%32];" \
        : "=r"((r)[0]),  "=r"((r)[1]),  "=r"((r)[2]),  "=r"((r)[3]), \
          "=r"((r)[4]),  "=r"((r)[5]),  "=r"((r)[6]),  "=r"((r)[7]), \
          "=r"((r)[8]),  "=r"((r)[9]),  "=r"((r)[10]), "=r"((r)[11]), \
          "=r"((r)[12]), "=r"((r)[13]), "=r"((r)[14]), "=r"((r)[15]), \
          "=r"((r)[16]), "=r"((r)[17]), "=r"((r)[18]), "=r"((r)[19]), \
          "=r"((r)[20]), "=r"((r)[21]), "=r"((r)[22]), "=r"((r)[23]), \
          "=r"((r)[24]), "=r"((r)[25]), "=r"((r)[26]), "=r"((r)[27]), \
          "=r"((r)[28]), "=r"((r)[29]), "=r"((r)[30]), "=r"((r)[31]) \
        : "r"(tmem_addr))

__device__ __forceinline__ void mma_tf32_ss(uint32_t d, uint64_t ad, uint64_t bd,
                                            uint32_t idesc, uint32_t en)
{
    asm volatile(
        "{\n\t.reg .pred p;\n\tsetp.ne.u32 p, %4, 0;\n\t"
        "tcgen05.mma.cta_group::1.kind::tf32 [%0], %1, %2, %3, {%5,%5,%5,%5}, p;\n\t}"
        :: "r"(d), "l"(ad), "l"(bd), "r"(idesc), "r"(en), "r"(0u)
        : "memory");
}
#endif

#define FENCE_PROXY_ASYNC() \
    asm volatile("fence.proxy.async.shared::cta;" ::: "memory")

// SMEM descriptor: SW128, version=1 (Blackwell), LBO=1, SBO=64
static __device__ __forceinline__ uint64_t make_desc_sw128(uint32_t base_addr)
{
    const uint64_t base =
        (uint64_t(2)  << 61) | (uint64_t(1) << 46) | (uint64_t(64) << 32) | (uint64_t(1) << 16);
    return base | ((uint64_t)(base_addr >> 4) & 0x3FFF);
}

#define SWZ128(off) ((off) ^ (((off) >> 3) & 0x70))

// ---------------- GEMM: C[M,N] = A[M,K] @ Bt[N,K]^T ------------------------------
// sm_103a: tcgen05 tf32, CTA tile 128x256, 3-stage cp.async pipeline
// fallback (plain sm_103 PTX pass): legacy mma.sync tf32, two 128x128 halves
#define GBM 128
#define GBN 256
#define GBK 32
#define A_ST 16384              // 128 rows * 128B
#define B_ST 32768              // 256 rows * 128B
#define ST_BYTES (A_ST + B_ST)  // 49152
#define SMEM_TC (2048 + 3 * ST_BYTES)

static constexpr uint32_t IDESC_TF32 =
    (1u << 4) | (2u << 7) | (2u << 10) | ((GBN / 8) << 17) | ((GBM / 16) << 24);

__global__ __launch_bounds__(256)
void gemm_tc(const float* __restrict__ A, const float* __restrict__ Bt,
             float* __restrict__ C, int M, int N, int K)
{
    extern __shared__ char smraw[];

#if HAVE_TCGEN05
    uint32_t raw;
    asm("{ .reg .u64 t; cvta.to.shared.u64 t, %1; cvt.u32.u64 %0, t; }"
        : "=r"(raw) : "l"(smraw));
    const uint32_t base = (raw + 1023u) & ~1023u;

    const int tid = threadIdx.x;
    const int warp = tid >> 5, lane = tid & 31;
    const int rowBase = blockIdx.y * GBM;
    const int colBase = blockIdx.x * GBN;
    const int nt = K / GBK;

    if (warp == 0) TCGEN05_ALLOC(base, 256);
    if (tid == 0) {
        MBARRIER_INIT(base + 8, 1);
        MBARRIER_INIT(base + 16, 1);
        MBARRIER_INIT(base + 24, 1);
    }
    __syncthreads();
    uint32_t tmem;
    asm volatile("ld.shared.b32 %0, [%1];" : "=r"(tmem) : "r"(base));

    auto loadTile = [&](int kt, int st) {
        uint32_t aBase = base + 1024 + st * ST_BYTES;
        uint32_t bBase = aBase + A_ST;
        const float* Ak = A + (size_t)rowBase * K + kt * GBK;
        const float* Bk = Bt + (size_t)colBase * K + kt * GBK;
#pragma unroll
        for (int i = 0; i < 4; i++) {
            int idx = tid + i * 256;          // 0..1023
            int r = idx >> 3, c = idx & 7;
            uint32_t off = (uint32_t)(r * 128 + c * 16);
            cpasync16(aBase + SWZ128(off), Ak + (size_t)r * K + c * 4);
        }
#pragma unroll
        for (int i = 0; i < 8; i++) {
            int idx = tid + i * 256;          // 0..2047
            int r = idx >> 3, c = idx & 7;
            uint32_t off = (uint32_t)(r * 128 + c * 16);
            cpasync16(bBase + SWZ128(off), Bk + (size_t)r * K + c * 4);
        }
        asm volatile("cp.async.commit_group;\n");
    };

    loadTile(0, 0);
    loadTile(1, 1);

    uint32_t ph = 0;                 // per-stage mma-commit phase bits
    for (int kt = 0; kt < nt; kt++) {
        int st = kt % 3;
        int ld = kt + 2;
        if (ld < nt) {
            int ls = ld % 3;
            if (ld >= 3) {           // stage ls last used by tile ld-3; wait its mma
                MBARRIER_WAIT_PARITY(base + 8 + ls * 8, (ph >> ls) & 1);
                ph ^= 1u << ls;
            }
            loadTile(ld, ls);
        }
        // wait until the group for tile kt has landed: depth = groups issued after it
        if (kt + 2 < nt)      asm volatile("cp.async.wait_group 2;\n");
        else if (kt + 1 < nt) asm volatile("cp.async.wait_group 1;\n");
        else                  asm volatile("cp.async.wait_group 0;\n");
        FENCE_PROXY_ASYNC();
        __syncthreads();

        if (warp == 0) {
            TCGEN05_FENCE_AFTER();
            if (elect_one_pred()) {
                uint32_t aBase = base + 1024 + st * ST_BYTES;
                uint64_t ad = make_desc_sw128(aBase);
                uint64_t bd = make_desc_sw128(aBase + A_ST);
#pragma unroll
                for (int ks = 0; ks < 4; ks++)
                    mma_tf32_ss(tmem, ad + ks * 2, bd + ks * 2, IDESC_TF32,
                                (kt > 0 || ks > 0) ? 1u : 0u);
                TCGEN05_COMMIT(base + 8 + st * 8);
            }
        }
    }

    {
        int ls = (nt - 1) % 3;
        MBARRIER_WAIT_PARITY(base + 8 + ls * 8, (ph >> ls) & 1);
    }
    TCGEN05_FENCE_AFTER();

    // epilogue: warp w -> rows (w%4)*32, cols (w/4)*128
    {
        int wr = warp & 3, wc = warp >> 2;
        int row = rowBase + wr * 32 + lane;
#pragma unroll
        for (int cb = 0; cb < 128; cb += 32) {
            uint32_t regs[32];
            TCGEN05_LD_32X32B_X32(regs, tmem + wc * 128 + cb);
            TCGEN05_WAIT_LD();
            float* cp = C + (size_t)row * N + colBase + wc * 128 + cb;
#pragma unroll
            for (int i = 0; i < 8; i++) {
                float4 v = make_float4(__uint_as_float(regs[i*4]), __uint_as_float(regs[i*4+1]),
                                       __uint_as_float(regs[i*4+2]), __uint_as_float(regs[i*4+3]));
                *(float4*)(cp + i * 4) = v;
            }
        }
    }
    TCGEN05_FENCE_BEFORE();
    __syncthreads();
    if (warp == 0) TCGEN05_DEALLOC(tmem, 256);

#else
    // ---------- legacy mma.sync tf32 fallback (valid on plain sm_103 target) -----
    float* smf = (float*)smraw;
    const uint32_t smBase = (uint32_t)__cvta_generic_to_shared(smf);
    const int tid = threadIdx.x;
    const int lane = tid & 31, warp = tid >> 5;
    const int wm = warp >> 2, wn = warp & 3;       // 2 x 4 warp grid
    const int lq = lane >> 2, lr = lane & 3;
    const int rowBase = blockIdx.y * GBM;
    const int FSPAD = 36;
    const int FSBUF = 128 * 36;

    for (int nh = 0; nh < 2; nh++) {
        const int colBase = blockIdx.x * GBN + nh * 128;

        float acc[4][4][4];
#pragma unroll
        for (int i = 0; i < 4; i++)
#pragma unroll
            for (int j = 0; j < 4; j++)
#pragma unroll
                for (int r = 0; r < 4; r++) acc[i][j][r] = 0.f;

        const int ntiles = K / 32;

        auto issue = [&](int kt, int buf) {
#pragma unroll
            for (int c = 0; c < 4; c++) {
                int idx = tid + c * 256;
                int r = idx >> 3, k4 = (idx & 7) * 4;
                cpasync16(smBase + (uint32_t)((buf * FSBUF + r * FSPAD + k4) * 4),
                          A + (size_t)(rowBase + r) * K + kt * 32 + k4);
                cpasync16(smBase + (uint32_t)(((2 + buf) * FSBUF + r * FSPAD + k4) * 4),
                          Bt + (size_t)(colBase + r) * K + kt * 32 + k4);
            }
            asm volatile("cp.async.commit_group;\n");
        };

        issue(0, 0);

        for (int kt = 0; kt < ntiles; kt++) {
            int buf = kt & 1;
            if (kt + 1 < ntiles) {
                issue(kt + 1, buf ^ 1);
                asm volatile("cp.async.wait_group 1;\n");
            } else {
                asm volatile("cp.async.wait_group 0;\n");
            }
            __syncthreads();

            const float* as = smf + buf * FSBUF;
            const float* bs = smf + (2 + buf) * FSBUF;
#pragma unroll
            for (int ks = 0; ks < 4; ks++) {
                const int kb = ks * 8 + lr;
                float a[4][4];
#pragma unroll
                for (int mf = 0; mf < 4; mf++) {
                    const float* p0 = as + (wm * 64 + mf * 16 + lq) * FSPAD;
                    a[mf][0] = p0[kb];
                    a[mf][1] = p0[8 * FSPAD + kb];
                    a[mf][2] = p0[kb + 4];
                    a[mf][3] = p0[8 * FSPAD + kb + 4];
                }
                float b[4][2];
#pragma unroll
                for (int nf = 0; nf < 4; nf++) {
                    const float* p0 = bs + (wn * 32 + nf * 8 + lq) * FSPAD;
                    b[nf][0] = p0[kb];
                    b[nf][1] = p0[kb + 4];
                }
#pragma unroll
                for (int mf = 0; mf < 4; mf++)
#pragma unroll
                    for (int nf = 0; nf < 4; nf++)
                        mma_tf32_frag(acc[mf][nf], a[mf], b[nf]);
            }
            __syncthreads();
        }

#pragma unroll
        for (int mf = 0; mf < 4; mf++) {
#pragma unroll
            for (int nf = 0; nf < 4; nf++) {
                int r = rowBase + wm * 64 + mf * 16 + lq;
                int c = colBase + wn * 32 + nf * 8 + lr * 2;
                *(float2*)&C[(size_t)r * N + c]       = make_float2(acc[mf][nf][0], acc[mf][nf][1]);
                *(float2*)&C[(size_t)(r + 8) * N + c] = make_float2(acc[mf][nf][2], acc[mf][nf][3]);
            }
        }
        __syncthreads();
    }
#endif
}

// ---------------- elementwise tf32 round ----------------------------------------
__global__ void kRound(const float4* __restrict__ src, float4* __restrict__ dst)
{
    int i = blockIdx.x * 256 + threadIdx.x;
    float4 v = src[i];
    v.x = tf32r(v.x); v.y = tf32r(v.y); v.z = tf32r(v.z); v.w = tf32r(v.w);
    dst[i] = v;
}

// ---------------- tiled transpose + round ----------------------------------------
__global__ void kTransRound(const float* __restrict__ src, float* __restrict__ dst,
                            int R, int C, size_t sStride, size_t dStride)
{
    __shared__ float t[32][33];
    const float* s = src + blockIdx.z * sStride;
    float* d = dst + blockIdx.z * dStride;
    int c0 = blockIdx.x * 32, r0 = blockIdx.y * 32;
#pragma unroll
    for (int i = 0; i < 32; i += 8) {
        t[threadIdx.y + i][threadIdx.x] = s[(size_t)(r0 + threadIdx.y + i) * C + c0 + threadIdx.x];
    }
    __syncthreads();
#pragma unroll
    for (int i = 0; i < 32; i += 8) {
        d[(size_t)(c0 + threadIdx.y + i) * R + r0 + threadIdx.x] =
            tf32r(t[threadIdx.x][threadIdx.y + i]);
    }
}

// ---------------- s1/s2 ----------------------------------------------------------
__global__ void kComputeS(const float* __restrict__ Wh, const float* __restrict__ a1,
                          const float* __restrict__ a2, float* s1, float* s2)
{
    int w = (blockIdx.x * blockDim.x + threadIdx.x) >> 5;
    int lane = threadIdx.x & 31;
    int n = w >> 3, h = w & 7;
    float4 v  = *(const float4*)(Wh + (size_t)n * GH + h * HDIM + lane * 4);
    float4 x1 = *(const float4*)(a1 + h * HDIM + lane * 4);
    float4 x2 = *(const float4*)(a2 + h * HDIM + lane * 4);
    float d1 = v.x * x1.x + v.y * x1.y + v.z * x1.z + v.w * x1.w;
    float d2 = v.x * x2.x + v.y * x2.y + v.z * x2.z + v.w * x2.w;
#pragma unroll
    for (int o = 16; o; o >>= 1) {
        d1 += __shfl_xor_sync(~0u, d1, o);
        d2 += __shfl_xor_sync(~0u, d2, o);
    }
    if (!lane) { s1[h * NNODE + n] = d1; s2[h * NNODE + n] = d2; }
}

// ---------------- CSR build ------------------------------------------------------
__global__ void kCsrCount(const float* __restrict__ adj, int* cnt)
{
    int w = (blockIdx.x * blockDim.x + threadIdx.x) >> 5;
    int lane = threadIdx.x & 31;
    if (w >= NNODE) return;
    int c = 0;
    for (int j = lane; j < NNODE; j += 32) c += (adj[(size_t)w * NNODE + j] > 0.f);
#pragma unroll
    for (int o = 16; o; o >>= 1) c += __shfl_xor_sync(~0u, c, o);
    if (!lane) cnt[w] = c;
}

__global__ void kScan(const int* __restrict__ cnt, int* off)
{
    __shared__ int sh[257];
    int t = threadIdx.x;
    int base = t * 8;
    int local[8], s = 0;
#pragma unroll
    for (int i = 0; i < 8; i++) { local[i] = cnt[base + i]; s += local[i]; }
    sh[t] = s;
    __syncthreads();
    if (t == 0) {
        int run = 0;
        for (int i = 0; i < 256; i++) { int v = sh[i]; sh[i] = run; run += v; }
        sh[256] = run;
    }
    __syncthreads();
    int run = sh[t];
#pragma unroll
    for (int i = 0; i < 8; i++) { off[base + i] = run; run += local[i]; }
    if (t == 255) off[NNODE] = sh[256];
}

__global__ void kCsrFill(const float* __restrict__ adj, const int* __restrict__ off, int* cols)
{
    int w = (blockIdx.x * blockDim.x + threadIdx.x) >> 5;
    int lane = threadIdx.x & 31;
    if (w >= NNODE) return;
    int base = off[w];
    for (int c0 = 0; c0 < NNODE; c0 += 32) {
        bool p = adj[(size_t)w * NNODE + c0 + lane] > 0.f;
        unsigned m = __ballot_sync(~0u, p);
        if (p) cols[base + __popc(m & ((1u << lane) - 1u))] = c0 + lane;
        base += __popc(m);
    }
}

// ---------------- sparse GAT attention -------------------------------------------
__global__ void kAttn(const float* __restrict__ Wh, const float* __restrict__ s1,
                      const float* __restrict__ s2, const int* __restrict__ off,
                      const int* __restrict__ cols, float* __restrict__ out)
{
    int n = blockIdx.x;
    int h = threadIdx.x >> 5, lane = threadIdx.x & 31;
    int o0 = off[n], o1 = off[n + 1];
    float sv = s1[h * NNODE + n];

    float mx = -INFINITY;
    for (int i = o0 + lane; i < o1; i += 32) {
        float e = sv + s2[h * NNODE + cols[i]];
        e = e > 0.f ? e : 0.2f * e;
        mx = fmaxf(mx, e);
    }
#pragma unroll
    for (int o = 16; o; o >>= 1) mx = fmaxf(mx, __shfl_xor_sync(~0u, mx, o));

    float a0 = 0.f, a1 = 0.f, a2 = 0.f, a3 = 0.f, sum = 0.f;
    for (int i = o0; i < o1; i++) {
        int j = cols[i];
        float e = sv + s2[h * NNODE + j];
        e = e > 0.f ? e : 0.2f * e;
        float wgt = expf(e - mx);
        sum += wgt;
        float4 v = *(const float4*)(Wh + (size_t)j * GH + h * HDIM + lane * 4);
        a0 = fmaf(wgt, v.x, a0); a1 = fmaf(wgt, v.y, a1);
        a2 = fmaf(wgt, v.z, a2); a3 = fmaf(wgt, v.w, a3);
    }
    float inv = 1.f / sum;
    float4 r = make_float4(a0 * inv, a1 * inv, a2 * inv, a3 * inv);
    *(float4*)(out + (size_t)n * GH + h * HDIM + lane * 4) = r;
}

// ---------------- block reduce helper --------------------------------------------
__device__ __forceinline__ float blockReduceSum(float v, float* red)
{
    int t = threadIdx.x;
    red[t] = v; __syncthreads();
    for (int st = 128; st; st >>= 1) { if (t < st) red[t] += red[t + st]; __syncthreads(); }
    float r = red[0];
    __syncthreads();
    return r;
}

__global__ void kLnEluRes(const float* __restrict__ hin, const float* __restrict__ g,
                          const float* __restrict__ b, float* __restrict__ x)
{
    __shared__ float red[256];
    int n = blockIdx.x, t = threadIdx.x;
    float4 v = ((const float4*)(hin + (size_t)n * GH))[t];
    float mu = blockReduceSum(v.x + v.y + v.z + v.w, red) * (1.f / GH);
    float dx0 = v.x - mu, dx1 = v.y - mu, dx2 = v.z - mu, dx3 = v.w - mu;
    float var = blockReduceSum(dx0*dx0 + dx1*dx1 + dx2*dx2 + dx3*dx3, red) * (1.f / GH);
    float rs = rsqrtf(var + 1e-5f);
    int c = t * 4;
    float4 gg = *(const float4*)(g + c), bb = *(const float4*)(b + c);
    float y0 = dx0 * rs * gg.x + bb.x, y1 = dx1 * rs * gg.y + bb.y;
    float y2 = dx2 * rs * gg.z + bb.z, y3 = dx3 * rs * gg.w + bb.w;
    y0 = y0 > 0.f ? y0 : expm1f(y0); y1 = y1 > 0.f ? y1 : expm1f(y1);
    y2 = y2 > 0.f ? y2 : expm1f(y2); y3 = y3 > 0.f ? y3 : expm1f(y3);
    float4* xp = (float4*)(x + (size_t)n * GH) + t;
    float4 xv = *xp;
    xv.x += y0; xv.y += y1; xv.z += y2; xv.w += y3;
    *xp = xv;
}

__global__ void kLnGelu(const float* __restrict__ C, const float* __restrict__ b1,
                        const float* __restrict__ g, const float* __restrict__ beta,
                        float* __restrict__ out)
{
    __shared__ float red[256];
    int n = blockIdx.x, t = threadIdx.x;
    int c = t * 4;
    float4 v = ((const float4*)(C + (size_t)n * ED))[t];
    float4 bv = *(const float4*)(b1 + c);
    v.x += bv.x; v.y += bv.y; v.z += bv.z; v.w += bv.w;
    float mu = blockReduceSum(v.x + v.y + v.z + v.w, red) * (1.f / ED);
    float d0 = v.x - mu, d1 = v.y - mu, d2 = v.z - mu, d3 = v.w - mu;
    float var = blockReduceSum(d0*d0 + d1*d1 + d2*d2 + d3*d3, red) * (1.f / ED);
    float rs = rsqrtf(var + 1e-5f);
    float4 gg = *(const float4*)(g + c), be = *(const float4*)(beta + c);
    float y0 = d0 * rs * gg.x + be.x, y1 = d1 * rs * gg.y + be.y;
    float y2 = d2 * rs * gg.z + be.z, y3 = d3 * rs * gg.w + be.w;
    const float k = 0.70710678118654752f;
    y0 = 0.5f * y0 * (1.f + erff(y0 * k)); y1 = 0.5f * y1 * (1.f + erff(y1 * k));
    y2 = 0.5f * y2 * (1.f + erff(y2 * k)); y3 = 0.5f * y3 * (1.f + erff(y3 * k));
    ((float4*)(out + (size_t)n * ED))[t] =
        make_float4(tf32r(y0), tf32r(y1), tf32r(y2), tf32r(y3));
}

__global__ void kBiasL2(const float* __restrict__ C, const float* __restrict__ b2,
                        float* __restrict__ out)
{
    __shared__ float red[256];
    int n = blockIdx.x, t = threadIdx.x;
    int c = t * 4;
    float4 v = ((const float4*)(C + (size_t)n * ED))[t];
    float4 bv = *(const float4*)(b2 + c);
    v.x += bv.x; v.y += bv.y; v.z += bv.z; v.w += bv.w;
    float ss = blockReduceSum(v.x*v.x + v.y*v.y + v.z*v.z + v.w*v.w, red);
    float inv = 1.f / fmaxf(sqrtf(ss), 1e-12f);
    ((float4*)(out + (size_t)n * ED))[t] =
        make_float4(tf32r(v.x*inv), tf32r(v.y*inv), tf32r(v.z*inv), tf32r(v.w*inv));
}

__global__ void kBiasAdd(const float* __restrict__ C, const float* __restrict__ bias,
                         float* __restrict__ out, int ncols, int total)
{
    int i = blockIdx.x * 256 + threadIdx.x;
    if (i < total) out[i] = C[i] + bias[i % ncols];
}

__global__ void kLse(const float* __restrict__ neg, float* __restrict__ rowv)
{
    __shared__ float red[256];
    int i = blockIdx.x, t = threadIdx.x;
    const float invT = 1.f / TEMPR;
    float pos = neg[(size_t)i * BB + i] * invT;
    float4 v = ((const float4*)(neg + (size_t)i * BB))[t];
    v.x *= invT; v.y *= invT; v.z *= invT; v.w *= invT;
    float m = fmaxf(fmaxf(v.x, v.y), fmaxf(v.z, v.w));
    m = fmaxf(m, pos);
    red[t] = m; __syncthreads();
    for (int st = 128; st; st >>= 1) { if (t < st) red[t] = fmaxf(red[t], red[t + st]); __syncthreads(); }
    float M = red[0];
    __syncthreads();
    float s = expf(v.x - M) + expf(v.y - M) + expf(v.z - M) + expf(v.w - M);
    float S = blockReduceSum(s, red);
    if (t == 0) rowv[i] = M + logf(S + expf(pos - M)) - pos;
}

__global__ void kMeanRow(const float* __restrict__ rowv, float* scal)
{
    __shared__ float red[256];
    int t = threadIdx.x;
    float s = rowv[t] + rowv[t + 256] + rowv[t + 512] + rowv[t + 768];
    float S = blockReduceSum(s, red);
    if (t == 0) scal[0] = S / (float)BB;
}

__global__ void kDotPart(const float* __restrict__ a, const float* __restrict__ b,
                         float* part, int n)
{
    __shared__ float red[256];
    float s = 0.f;
    for (int i = blockIdx.x * 256 + threadIdx.x; i < n; i += 256 * 256) s = fmaf(a[i], b[i], s);
    float S = blockReduceSum(s, red);
    if (threadIdx.x == 0) part[blockIdx.x] = S;
}

__global__ void kDotFinal(const float* __restrict__ part, float* scal)
{
    __shared__ float red[256];
    float S = blockReduceSum(part[threadIdx.x], red);
    if (threadIdx.x == 0) scal[1] = S / (float)NNODE;
}

__global__ void kFinal(const float* __restrict__ scal, float* out, int n)
{
    if (threadIdx.x == 0) {
        float inf_nce = scal[0], lap = scal[1];
        if (n > 0) out[0] = inf_nce + LAPW * lap;
        if (n > 1) out[1] = inf_nce;
        if (n > 2) out[2] = lap;
    }
}

// ---------------- host -----------------------------------------------------------
static inline void* sym(const void* s) { void* p = nullptr; cudaGetSymbolAddress(&p, s); return p; }

static void gemm(const float* A, const float* Bt, float* C, int M, int N, int K)
{
    dim3 grid(N / GBN, M / GBM);
    gemm_tc<<<grid, 256, SMEM_TC>>>(A, Bt, C, M, N, K);
}

extern "C" void kernel_launch(void* const* d_in, const int* in_sizes, int n_in,
                              void* d_out, int out_size)
{
    const float* query = (const float*)d_in[0];
    const float* docs  = (const float*)d_in[1];
    const float* nodes = (const float*)d_in[2];
    const float* adj   = (const float*)d_in[3];
    const float* lapM  = (const float*)d_in[4];
    const float* qW1 = (const float*)d_in[5];  const float* qb1 = (const float*)d_in[6];
    const float* qg  = (const float*)d_in[7];  const float* qbt = (const float*)d_in[8];
    const float* qW2 = (const float*)d_in[9];  const float* qb2 = (const float*)d_in[10];
    const float* dW1 = (const float*)d_in[11]; const float* db1 = (const float*)d_in[12];
    const float* dg  = (const float*)d_in[13]; const float* dbt = (const float*)d_in[14];
    const float* dW2 = (const float*)d_in[15]; const float* db2 = (const float*)d_in[16];
    const float* gatW = (const float*)d_in[17];
    const float* a1 = (const float*)d_in[18];
    const float* a2 = (const float*)d_in[19];
    const float* ln_g = (const float*)d_in[20];
    const float* ln_b = (const float*)d_in[21];
    const float* poW = (const float*)d_in[22];
    const float* pob = (const float*)d_in[23];

    float* x    = (float*)sym(g_x);
    float* xr   = (float*)sym(g_xr);
    float* Wh   = (float*)sym(g_Wh);
    float* Wcat = (float*)sym(g_Wcat);
    float* wT   = (float*)sym(g_wT);
    float* lapr = (float*)sym(g_lapr);
    float* geT  = (float*)sym(g_geT);
    float* s1   = (float*)sym(g_s1);
    float* s2   = (float*)sym(g_s2);
    float* hb   = (float*)sym(g_hb);
    int*   cnt  = (int*)sym(g_cnt);
    int*   off  = (int*)sym(g_off);
    int*   cols = (int*)sym(g_cols);
    float* ge   = (float*)sym(g_ge);
    float* tb   = (float*)sym(g_t);
    float* tmp1 = (float*)sym(g_tmp1);
    float* tmp2 = (float*)sym(g_tmp2);
    float* q    = (float*)sym(g_q);
    float* p    = (float*)sym(g_p);
    float* neg  = (float*)sym(g_neg);
    float* rowv = (float*)sym(g_rowv);
    float* part = (float*)sym(g_part);
    float* scal = (float*)sym(g_scal);

    cudaFuncSetAttribute(gemm_tc, cudaFuncAttributeMaxDynamicSharedMemorySize, SMEM_TC);

    // init node state
    cudaMemcpyAsync(x, nodes, (size_t)NNODE * ED * sizeof(float), cudaMemcpyDeviceToDevice);

    // CSR from adj
    kCsrCount<<<NNODE / 8, 256>>>(adj, cnt);
    kScan<<<1, 256>>>(cnt, off);
    kCsrFill<<<NNODE / 8, 256>>>(adj, off, cols);

    // round laplacian once
    kRound<<<(NNODE * NNODE) / 1024, 256>>>((const float4*)lapM, (float4*)lapr);

    dim3 tb32(32, 8);

    for (int l = 0; l < NLAY; l++) {
        kTransRound<<<dim3(HDIM / 32, ED / 32, NHEAD), tb32>>>(
            gatW + (size_t)l * NHEAD * ED * HDIM, Wcat, ED, HDIM,
            (size_t)ED * HDIM, (size_t)HDIM * ED);
        kRound<<<(NNODE * GH) / 1024, 256>>>((const float4*)x, (float4*)xr);
        gemm(xr, Wcat, Wh, NNODE, GH, ED);
        kComputeS<<<(NNODE * NHEAD) / 8, 256>>>(Wh, a1 + (size_t)l * NHEAD * HDIM,
                                                a2 + (size_t)l * NHEAD * HDIM, s1, s2);
        kAttn<<<NNODE, 256>>>(Wh, s1, s2, off, cols, hb);
        kLnEluRes<<<NNODE, 256>>>(hb, ln_g + (size_t)l * GH, ln_b + (size_t)l * GH, x);
    }

    // graph embeds = x @ poW + pob
    kTransRound<<<dim3(ED / 32, GH / 32), tb32>>>(poW, wT, GH, ED, 0, 0);
    kRound<<<(NNODE * GH) / 1024, 256>>>((const float4*)x, (float4*)xr);
    gemm(xr, wT, tb, NNODE, ED, GH);
    kBiasAdd<<<(NNODE * ED) / 256, 256>>>(tb, pob, ge, ED, NNODE * ED);

    // query tower
    kRound<<<(BB * ED) / 1024, 256>>>((const float4*)query, (float4*)xr);
    kTransRound<<<dim3(ED / 32, ED / 32), tb32>>>(qW1, wT, ED, ED, 0, 0);
    gemm(xr, wT, tmp1, BB, ED, ED);
    kLnGelu<<<BB, 256>>>(tmp1, qb1, qg, qbt, tmp2);
    kTransRound<<<dim3(ED / 32, ED / 32), tb32>>>(qW2, wT, ED, ED, 0, 0);
    gemm(tmp2, wT, tmp1, BB, ED, ED);
    kBiasL2<<<BB, 256>>>(tmp1, qb2, q);

    // doc tower
    kRound<<<(BB * ED) / 1024, 256>>>((const float4*)docs, (float4*)xr);
    kTransRound<<<dim3(ED / 32, ED / 32), tb32>>>(dW1, wT, ED, ED, 0, 0);
    gemm(xr, wT, tmp1, BB, ED, ED);
    kLnGelu<<<BB, 256>>>(tmp1, db1, dg, dbt, tmp2);
    kTransRound<<<dim3(ED / 32, ED / 32), tb32>>>(dW2, wT, ED, ED, 0, 0);
    gemm(tmp2, wT, tmp1, BB, ED, ED);
    kBiasL2<<<BB, 256>>>(tmp1, db2, p);

    // similarities + InfoNCE
    gemm(q, p, neg, BB, BB, ED);
    kLse<<<BB, 256>>>(neg, rowv);
    kMeanRow<<<1, 256>>>(rowv, scal);

    // laplacian term
    kTransRound<<<dim3(ED / 32, NNODE / 32), tb32>>>(ge, geT, NNODE, ED, 0, 0);
    gemm(lapr, geT, tb, NNODE, ED, NNODE);
    kDotPart<<<256, 256>>>(ge, tb, part, NNODE * ED);
    kDotFinal<<<1, 256>>>(part, scal);

    kFinal<<<1, 32>>>(scal, (float*)d_out, out_size);
}

// round 13
// speedup vs baseline: 1.4357x; 1.4357x over previous
#include <cuda_runtime.h>
#include <math.h>
#include <stdint.h>

#define ED   1024
#define GH   1024
#define NLAY 3
#define NHEAD 8
#define HDIM 128
#define NNODE 2048
#define BB   1024
#define TEMPR 0.05f
#define LAPW 0.1f

// ---------------- scratch (device globals; no allocation allowed) ----------------
__device__ float g_x[NNODE * GH];
__device__ float g_xr[NNODE * GH];
__device__ float g_Wh[NNODE * GH];
__device__ float g_Wcat[GH * ED];
__device__ float g_wT[ED * GH];
__device__ float g_lapr[NNODE * NNODE];
__device__ float g_geT[ED * NNODE];
__device__ float g_s1[NHEAD * NNODE];
__device__ float g_s2[NHEAD * NNODE];
__device__ float g_hb[NNODE * GH];
__device__ int   g_cnt[NNODE];
__device__ int   g_off[NNODE + 1];
__device__ int   g_cols[NNODE * 256];
__device__ float g_ge[NNODE * ED];
__device__ float g_t[NNODE * ED];
__device__ float g_tmp1[BB * ED];
__device__ float g_tmp2[BB * ED];
__device__ float g_q[BB * ED];
__device__ float g_p[BB * ED];
__device__ float g_neg[BB * BB];
__device__ float g_rowv[BB];
__device__ float g_part[256];
__device__ float g_scal[2];

// ---------------- helpers ---------------------------------------------------------
__device__ __forceinline__ float tf32r(float x)
{
    float y;
    asm("cvt.rna.tf32.f32 %0, %1;" : "=f"(y) : "f"(x));
    return y;
}

__device__ __forceinline__ void cpasync16(uint32_t dst, const void* src)
{
    asm volatile("cp.async.cg.shared.global [%0], [%1], 16;\n" :: "r"(dst), "l"(src));
}

__device__ __forceinline__ void mma_tf32_frag(float* d, const float* a, const float* b)
{
    asm volatile(
        "mma.sync.aligned.m16n8k8.row.col.f32.tf32.tf32.f32 "
        "{%0,%1,%2,%3}, {%4,%5,%6,%7}, {%8,%9}, {%0,%1,%2,%3};\n"
        : "+f"(d[0]), "+f"(d[1]), "+f"(d[2]), "+f"(d[3])
        : "r"(__float_as_uint(a[0])), "r"(__float_as_uint(a[1])),
          "r"(__float_as_uint(a[2])), "r"(__float_as_uint(a[3])),
          "r"(__float_as_uint(b[0])), "r"(__float_as_uint(b[1])));
}

// ---------------- legacy mma.sync tf32 GEMM: C = A @ Bt^T -------------------------
// Template MF: per-warp M-fragment count. BM = MF*32 (wm in {0,1}), BN = 128, BK = 32.
// MF=4 -> 128x128 tile (proven R2 geometry). MF=2 -> 64x128 tile for M=1024 GEMMs
// (doubles CTA count: 64 -> 128 CTAs on the towers, 86% of 148 SMs).
#define SPAD 36
#define GEMM_SMEM_MAX ((128 + 128) * SPAD * 2 * 4)   // MF=4 worst case: 73728 B

template <int MF>
__global__ __launch_bounds__(256)
void gemm_leg(const float* __restrict__ A, const float* __restrict__ Bt,
              float* __restrict__ C, int M, int N, int K)
{
    constexpr int BM = MF * 32;
    constexpr int ABUF = BM * SPAD;
    constexpr int BBUF = 128 * SPAD;
    extern __shared__ __align__(16) float smf[];
    // layout: [A0][A1][B0][B1]
    const uint32_t smBase = (uint32_t)__cvta_generic_to_shared(smf);

    const int tid = threadIdx.x;
    const int lane = tid & 31, warp = tid >> 5;
    const int wm = warp >> 2, wn = warp & 3;        // 2 x 4 warp grid
    const int lq = lane >> 2, lr = lane & 3;
    const int rowBase = blockIdx.y * BM;
    const int colBase = blockIdx.x * 128;

    float acc[MF][4][4];
#pragma unroll
    for (int i = 0; i < MF; i++)
#pragma unroll
        for (int j = 0; j < 4; j++)
#pragma unroll
            for (int r = 0; r < 4; r++) acc[i][j][r] = 0.f;

    const int ntiles = K / 32;

    auto issue = [&](int kt, int buf) {
#pragma unroll
        for (int c = 0; c < MF; c++) {               // A: BM*8 float4s
            int idx = tid + c * 256;
            int r = idx >> 3, k4 = (idx & 7) * 4;
            cpasync16(smBase + (uint32_t)((buf * ABUF + r * SPAD + k4) * 4),
                      A + (size_t)(rowBase + r) * K + kt * 32 + k4);
        }
#pragma unroll
        for (int c = 0; c < 4; c++) {                // B: 128*8 float4s
            int idx = tid + c * 256;
            int r = idx >> 3, k4 = (idx & 7) * 4;
            cpasync16(smBase + (uint32_t)((2 * ABUF + buf * BBUF + r * SPAD + k4) * 4),
                      Bt + (size_t)(colBase + r) * K + kt * 32 + k4);
        }
        asm volatile("cp.async.commit_group;\n");
    };

    issue(0, 0);

    for (int kt = 0; kt < ntiles; kt++) {
        int buf = kt & 1;
        if (kt + 1 < ntiles) {
            issue(kt + 1, buf ^ 1);
            asm volatile("cp.async.wait_group 1;\n");
        } else {
            asm volatile("cp.async.wait_group 0;\n");
        }
        __syncthreads();

        const float* as = smf + buf * ABUF;
        const float* bs = smf + 2 * ABUF + buf * BBUF;
#pragma unroll
        for (int ks = 0; ks < 4; ks++) {
            const int kb = ks * 8 + lr;
            float a[MF][4];
#pragma unroll
            for (int mf = 0; mf < MF; mf++) {
                const float* p0 = as + (wm * (MF * 16) + mf * 16 + lq) * SPAD;
                a[mf][0] = p0[kb];
                a[mf][1] = p0[8 * SPAD + kb];
                a[mf][2] = p0[kb + 4];
                a[mf][3] = p0[8 * SPAD + kb + 4];
            }
            float b[4][2];
#pragma unroll
            for (int nf = 0; nf < 4; nf++) {
                const float* p0 = bs + (wn * 32 + nf * 8 + lq) * SPAD;
                b[nf][0] = p0[kb];
                b[nf][1] = p0[kb + 4];
            }
#pragma unroll
            for (int mf = 0; mf < MF; mf++)
#pragma unroll
                for (int nf = 0; nf < 4; nf++)
                    mma_tf32_frag(acc[mf][nf], a[mf], b[nf]);
        }
        __syncthreads();
    }

#pragma unroll
    for (int mf = 0; mf < MF; mf++) {
#pragma unroll
        for (int nf = 0; nf < 4; nf++) {
            int r = rowBase + wm * (MF * 16) + mf * 16 + lq;
            int c = colBase + wn * 32 + nf * 8 + lr * 2;
            *(float2*)&C[(size_t)r * N + c]       = make_float2(acc[mf][nf][0], acc[mf][nf][1]);
            *(float2*)&C[(size_t)(r + 8) * N + c] = make_float2(acc[mf][nf][2], acc[mf][nf][3]);
        }
    }
}

// ---------------- elementwise tf32 round ----------------------------------------
__global__ void kRound(const float4* __restrict__ src, float4* __restrict__ dst)
{
    int i = blockIdx.x * 256 + threadIdx.x;
    float4 v = src[i];
    v.x = tf32r(v.x); v.y = tf32r(v.y); v.z = tf32r(v.z); v.w = tf32r(v.w);
    dst[i] = v;
}

// ---------------- tiled transpose + round ----------------------------------------
__global__ void kTransRound(const float* __restrict__ src, float* __restrict__ dst,
                            int R, int C, size_t sStride, size_t dStride)
{
    __shared__ float t[32][33];
    const float* s = src + blockIdx.z * sStride;
    float* d = dst + blockIdx.z * dStride;
    int c0 = blockIdx.x * 32, r0 = blockIdx.y * 32;
#pragma unroll
    for (int i = 0; i < 32; i += 8) {
        t[threadIdx.y + i][threadIdx.x] = s[(size_t)(r0 + threadIdx.y + i) * C + c0 + threadIdx.x];
    }
    __syncthreads();
#pragma unroll
    for (int i = 0; i < 32; i += 8) {
        d[(size_t)(c0 + threadIdx.y + i) * R + r0 + threadIdx.x] =
            tf32r(t[threadIdx.x][threadIdx.y + i]);
    }
}

// ---------------- s1/s2 ----------------------------------------------------------
__global__ void kComputeS(const float* __restrict__ Wh, const float* __restrict__ a1,
                          const float* __restrict__ a2, float* s1, float* s2)
{
    int w = (blockIdx.x * blockDim.x + threadIdx.x) >> 5;
    int lane = threadIdx.x & 31;
    int n = w >> 3, h = w & 7;
    float4 v  = *(const float4*)(Wh + (size_t)n * GH + h * HDIM + lane * 4);
    float4 x1 = *(const float4*)(a1 + h * HDIM + lane * 4);
    float4 x2 = *(const float4*)(a2 + h * HDIM + lane * 4);
    float d1 = v.x * x1.x + v.y * x1.y + v.z * x1.z + v.w * x1.w;
    float d2 = v.x * x2.x + v.y * x2.y + v.z * x2.z + v.w * x2.w;
#pragma unroll
    for (int o = 16; o; o >>= 1) {
        d1 += __shfl_xor_sync(~0u, d1, o);
        d2 += __shfl_xor_sync(~0u, d2, o);
    }
    if (!lane) { s1[h * NNODE + n] = d1; s2[h * NNODE + n] = d2; }
}

// ---------------- CSR build ------------------------------------------------------
__global__ void kCsrCount(const float* __restrict__ adj, int* cnt)
{
    int w = (blockIdx.x * blockDim.x + threadIdx.x) >> 5;
    int lane = threadIdx.x & 31;
    if (w >= NNODE) return;
    int c = 0;
    for (int j = lane; j < NNODE; j += 32) c += (adj[(size_t)w * NNODE + j] > 0.f);
#pragma unroll
    for (int o = 16; o; o >>= 1) c += __shfl_xor_sync(~0u, c, o);
    if (!lane) cnt[w] = c;
}

__global__ void kScan(const int* __restrict__ cnt, int* off)
{
    __shared__ int sh[257];
    int t = threadIdx.x;
    int base = t * 8;
    int local[8], s = 0;
#pragma unroll
    for (int i = 0; i < 8; i++) { local[i] = cnt[base + i]; s += local[i]; }
    sh[t] = s;
    __syncthreads();
    if (t == 0) {
        int run = 0;
        for (int i = 0; i < 256; i++) { int v = sh[i]; sh[i] = run; run += v; }
        sh[256] = run;
    }
    __syncthreads();
    int run = sh[t];
#pragma unroll
    for (int i = 0; i < 8; i++) { off[base + i] = run; run += local[i]; }
    if (t == 255) off[NNODE] = sh[256];
}

__global__ void kCsrFill(const float* __restrict__ adj, const int* __restrict__ off, int* cols)
{
    int w = (blockIdx.x * blockDim.x + threadIdx.x) >> 5;
    int lane = threadIdx.x & 31;
    if (w >= NNODE) return;
    int base = off[w];
    for (int c0 = 0; c0 < NNODE; c0 += 32) {
        bool p = adj[(size_t)w * NNODE + c0 + lane] > 0.f;
        unsigned m = __ballot_sync(~0u, p);
        if (p) cols[base + __popc(m & ((1u << lane) - 1u))] = c0 + lane;
        base += __popc(m);
    }
}

// ---------------- sparse GAT attention -------------------------------------------
__global__ void kAttn(const float* __restrict__ Wh, const float* __restrict__ s1,
                      const float* __restrict__ s2, const int* __restrict__ off,
                      const int* __restrict__ cols, float* __restrict__ out)
{
    int n = blockIdx.x;
    int h = threadIdx.x >> 5, lane = threadIdx.x & 31;
    int o0 = off[n], o1 = off[n + 1];
    float sv = s1[h * NNODE + n];

    float mx = -INFINITY;
    for (int i = o0 + lane; i < o1; i += 32) {
        float e = sv + s2[h * NNODE + cols[i]];
        e = e > 0.f ? e : 0.2f * e;
        mx = fmaxf(mx, e);
    }
#pragma unroll
    for (int o = 16; o; o >>= 1) mx = fmaxf(mx, __shfl_xor_sync(~0u, mx, o));

    float a0 = 0.f, a1 = 0.f, a2 = 0.f, a3 = 0.f, sum = 0.f;
    for (int i = o0; i < o1; i++) {
        int j = cols[i];
        float e = sv + s2[h * NNODE + j];
        e = e > 0.f ? e : 0.2f * e;
        float wgt = expf(e - mx);
        sum += wgt;
        float4 v = *(const float4*)(Wh + (size_t)j * GH + h * HDIM + lane * 4);
        a0 = fmaf(wgt, v.x, a0); a1 = fmaf(wgt, v.y, a1);
        a2 = fmaf(wgt, v.z, a2); a3 = fmaf(wgt, v.w, a3);
    }
    float inv = 1.f / sum;
    float4 r = make_float4(a0 * inv, a1 * inv, a2 * inv, a3 * inv);
    *(float4*)(out + (size_t)n * GH + h * HDIM + lane * 4) = r;
}

// ---------------- block reduce helper --------------------------------------------
__device__ __forceinline__ float blockReduceSum(float v, float* red)
{
    int t = threadIdx.x;
    red[t] = v; __syncthreads();
    for (int st = 128; st; st >>= 1) { if (t < st) red[t] += red[t + st]; __syncthreads(); }
    float r = red[0];
    __syncthreads();
    return r;
}

// x += elu(ln(hin)); ALSO writes tf32-rounded copy xr (fuses the per-layer kRound)
__global__ void kLnEluRes(const float* __restrict__ hin, const float* __restrict__ g,
                          const float* __restrict__ b, float* __restrict__ x,
                          float* __restrict__ xr)
{
    __shared__ float red[256];
    int n = blockIdx.x, t = threadIdx.x;
    float4 v = ((const float4*)(hin + (size_t)n * GH))[t];
    float mu = blockReduceSum(v.x + v.y + v.z + v.w, red) * (1.f / GH);
    float dx0 = v.x - mu, dx1 = v.y - mu, dx2 = v.z - mu, dx3 = v.w - mu;
    float var = blockReduceSum(dx0*dx0 + dx1*dx1 + dx2*dx2 + dx3*dx3, red) * (1.f / GH);
    float rs = rsqrtf(var + 1e-5f);
    int c = t * 4;
    float4 gg = *(const float4*)(g + c), bb = *(const float4*)(b + c);
    float y0 = dx0 * rs * gg.x + bb.x, y1 = dx1 * rs * gg.y + bb.y;
    float y2 = dx2 * rs * gg.z + bb.z, y3 = dx3 * rs * gg.w + bb.w;
    y0 = y0 > 0.f ? y0 : expm1f(y0); y1 = y1 > 0.f ? y1 : expm1f(y1);
    y2 = y2 > 0.f ? y2 : expm1f(y2); y3 = y3 > 0.f ? y3 : expm1f(y3);
    float4* xp = (float4*)(x + (size_t)n * GH) + t;
    float4 xv = *xp;
    xv.x += y0; xv.y += y1; xv.z += y2; xv.w += y3;
    *xp = xv;
    ((float4*)(xr + (size_t)n * GH))[t] =
        make_float4(tf32r(xv.x), tf32r(xv.y), tf32r(xv.z), tf32r(xv.w));
}

__global__ void kLnGelu(const float* __restrict__ C, const float* __restrict__ b1,
                        const float* __restrict__ g, const float* __restrict__ beta,
                        float* __restrict__ out)
{
    __shared__ float red[256];
    int n = blockIdx.x, t = threadIdx.x;
    int c = t * 4;
    float4 v = ((const float4*)(C + (size_t)n * ED))[t];
    float4 bv = *(const float4*)(b1 + c);
    v.x += bv.x; v.y += bv.y; v.z += bv.z; v.w += bv.w;
    float mu = blockReduceSum(v.x + v.y + v.z + v.w, red) * (1.f / ED);
    float d0 = v.x - mu, d1 = v.y - mu, d2 = v.z - mu, d3 = v.w - mu;
    float var = blockReduceSum(d0*d0 + d1*d1 + d2*d2 + d3*d3, red) * (1.f / ED);
    float rs = rsqrtf(var + 1e-5f);
    float4 gg = *(const float4*)(g + c), be = *(const float4*)(beta + c);
    float y0 = d0 * rs * gg.x + be.x, y1 = d1 * rs * gg.y + be.y;
    float y2 = d2 * rs * gg.z + be.z, y3 = d3 * rs * gg.w + be.w;
    const float k = 0.70710678118654752f;
    y0 = 0.5f * y0 * (1.f + erff(y0 * k)); y1 = 0.5f * y1 * (1.f + erff(y1 * k));
    y2 = 0.5f * y2 * (1.f + erff(y2 * k)); y3 = 0.5f * y3 * (1.f + erff(y3 * k));
    ((float4*)(out + (size_t)n * ED))[t] =
        make_float4(tf32r(y0), tf32r(y1), tf32r(y2), tf32r(y3));
}

__global__ void kBiasL2(const float* __restrict__ C, const float* __restrict__ b2,
                        float* __restrict__ out)
{
    __shared__ float red[256];
    int n = blockIdx.x, t = threadIdx.x;
    int c = t * 4;
    float4 v = ((const float4*)(C + (size_t)n * ED))[t];
    float4 bv = *(const float4*)(b2 + c);
    v.x += bv.x; v.y += bv.y; v.z += bv.z; v.w += bv.w;
    float ss = blockReduceSum(v.x*v.x + v.y*v.y + v.z*v.z + v.w*v.w, red);
    float inv = 1.f / fmaxf(sqrtf(ss), 1e-12f);
    ((float4*)(out + (size_t)n * ED))[t] =
        make_float4(tf32r(v.x*inv), tf32r(v.y*inv), tf32r(v.z*inv), tf32r(v.w*inv));
}

__global__ void kBiasAdd(const float* __restrict__ C, const float* __restrict__ bias,
                         float* __restrict__ out, int ncols, int total)
{
    int i = blockIdx.x * 256 + threadIdx.x;
    if (i < total) out[i] = C[i] + bias[i % ncols];
}

__global__ void kLse(const float* __restrict__ neg, float* __restrict__ rowv)
{
    __shared__ float red[256];
    int i = blockIdx.x, t = threadIdx.x;
    const float invT = 1.f / TEMPR;
    float pos = neg[(size_t)i * BB + i] * invT;
    float4 v = ((const float4*)(neg + (size_t)i * BB))[t];
    v.x *= invT; v.y *= invT; v.z *= invT; v.w *= invT;
    float m = fmaxf(fmaxf(v.x, v.y), fmaxf(v.z, v.w));
    m = fmaxf(m, pos);
    red[t] = m; __syncthreads();
    for (int st = 128; st; st >>= 1) { if (t < st) red[t] = fmaxf(red[t], red[t + st]); __syncthreads(); }
    float M = red[0];
    __syncthreads();
    float s = expf(v.x - M) + expf(v.y - M) + expf(v.z - M) + expf(v.w - M);
    float S = blockReduceSum(s, red);
    if (t == 0) rowv[i] = M + logf(S + expf(pos - M)) - pos;
}

__global__ void kMeanRow(const float* __restrict__ rowv, float* scal)
{
    __shared__ float red[256];
    int t = threadIdx.x;
    float s = rowv[t] + rowv[t + 256] + rowv[t + 512] + rowv[t + 768];
    float S = blockReduceSum(s, red);
    if (t == 0) scal[0] = S / (float)BB;
}

__global__ void kDotPart(const float* __restrict__ a, const float* __restrict__ b,
                         float* part, int n)
{
    __shared__ float red[256];
    float s = 0.f;
    for (int i = blockIdx.x * 256 + threadIdx.x; i < n; i += 256 * 256) s = fmaf(a[i], b[i], s);
    float S = blockReduceSum(s, red);
    if (threadIdx.x == 0) part[blockIdx.x] = S;
}

__global__ void kDotFinal(const float* __restrict__ part, float* scal)
{
    __shared__ float red[256];
    float S = blockReduceSum(part[threadIdx.x], red);
    if (threadIdx.x == 0) scal[1] = S / (float)NNODE;
}

__global__ void kFinal(const float* __restrict__ scal, float* out, int n)
{
    if (threadIdx.x == 0) {
        float inf_nce = scal[0], lap = scal[1];
        if (n > 0) out[0] = inf_nce + LAPW * lap;
        if (n > 1) out[1] = inf_nce;
        if (n > 2) out[2] = lap;
    }
}

// ---------------- host -----------------------------------------------------------
static inline void* sym(const void* s) { void* p = nullptr; cudaGetSymbolAddress(&p, s); return p; }

static void gemm(const float* A, const float* Bt, float* C, int M, int N, int K)
{
    if (M >= 2048) {
        dim3 grid(N / 128, M / 128);
        gemm_leg<4><<<grid, 256, GEMM_SMEM_MAX>>>(A, Bt, C, M, N, K);
    } else {
        dim3 grid(N / 128, M / 64);
        gemm_leg<2><<<grid, 256, (64 + 128) * SPAD * 2 * 4>>>(A, Bt, C, M, N, K);
    }
}

extern "C" void kernel_launch(void* const* d_in, const int* in_sizes, int n_in,
                              void* d_out, int out_size)
{
    const float* query = (const float*)d_in[0];
    const float* docs  = (const float*)d_in[1];
    const float* nodes = (const float*)d_in[2];
    const float* adj   = (const float*)d_in[3];
    const float* lapM  = (const float*)d_in[4];
    const float* qW1 = (const float*)d_in[5];  const float* qb1 = (const float*)d_in[6];
    const float* qg  = (const float*)d_in[7];  const float* qbt = (const float*)d_in[8];
    const float* qW2 = (const float*)d_in[9];  const float* qb2 = (const float*)d_in[10];
    const float* dW1 = (const float*)d_in[11]; const float* db1 = (const float*)d_in[12];
    const float* dg  = (const float*)d_in[13]; const float* dbt = (const float*)d_in[14];
    const float* dW2 = (const float*)d_in[15]; const float* db2 = (const float*)d_in[16];
    const float* gatW = (const float*)d_in[17];
    const float* a1 = (const float*)d_in[18];
    const float* a2 = (const float*)d_in[19];
    const float* ln_g = (const float*)d_in[20];
    const float* ln_b = (const float*)d_in[21];
    const float* poW = (const float*)d_in[22];
    const float* pob = (const float*)d_in[23];

    float* x    = (float*)sym(g_x);
    float* xr   = (float*)sym(g_xr);
    float* Wh   = (float*)sym(g_Wh);
    float* Wcat = (float*)sym(g_Wcat);
    float* wT   = (float*)sym(g_wT);
    float* lapr = (float*)sym(g_lapr);
    float* geT  = (float*)sym(g_geT);
    float* s1   = (float*)sym(g_s1);
    float* s2   = (float*)sym(g_s2);
    float* hb   = (float*)sym(g_hb);
    int*   cnt  = (int*)sym(g_cnt);
    int*   off  = (int*)sym(g_off);
    int*   cols = (int*)sym(g_cols);
    float* ge   = (float*)sym(g_ge);
    float* tb   = (float*)sym(g_t);
    float* tmp1 = (float*)sym(g_tmp1);
    float* tmp2 = (float*)sym(g_tmp2);
    float* q    = (float*)sym(g_q);
    float* p    = (float*)sym(g_p);
    float* neg  = (float*)sym(g_neg);
    float* rowv = (float*)sym(g_rowv);
    float* part = (float*)sym(g_part);
    float* scal = (float*)sym(g_scal);

    cudaFuncSetAttribute(gemm_leg<4>, cudaFuncAttributeMaxDynamicSharedMemorySize, GEMM_SMEM_MAX);
    cudaFuncSetAttribute(gemm_leg<2>, cudaFuncAttributeMaxDynamicSharedMemorySize,
                         (64 + 128) * SPAD * 2 * 4);

    // init node state
    cudaMemcpyAsync(x, nodes, (size_t)NNODE * ED * sizeof(float), cudaMemcpyDeviceToDevice);

    // CSR from adj
    kCsrCount<<<NNODE / 8, 256>>>(adj, cnt);
    kScan<<<1, 256>>>(cnt, off);
    kCsrFill<<<NNODE / 8, 256>>>(adj, off, cols);

    // round laplacian once
    kRound<<<(NNODE * NNODE) / 1024, 256>>>((const float4*)lapM, (float4*)lapr);

    // initial rounded copy of x (layer 0 input); later layers updated by kLnEluRes
    kRound<<<(NNODE * GH) / 1024, 256>>>((const float4*)nodes, (float4*)xr);

    dim3 tb32(32, 8);

    for (int l = 0; l < NLAY; l++) {
        kTransRound<<<dim3(HDIM / 32, ED / 32, NHEAD), tb32>>>(
            gatW + (size_t)l * NHEAD * ED * HDIM, Wcat, ED, HDIM,
            (size_t)ED * HDIM, (size_t)HDIM * ED);
        gemm(xr, Wcat, Wh, NNODE, GH, ED);
        kComputeS<<<(NNODE * NHEAD) / 8, 256>>>(Wh, a1 + (size_t)l * NHEAD * HDIM,
                                                a2 + (size_t)l * NHEAD * HDIM, s1, s2);
        kAttn<<<NNODE, 256>>>(Wh, s1, s2, off, cols, hb);
        kLnEluRes<<<NNODE, 256>>>(hb, ln_g + (size_t)l * GH, ln_b + (size_t)l * GH, x, xr);
    }

    // graph embeds = x @ poW + pob   (xr holds rounded x after layer 2)
    kTransRound<<<dim3(ED / 32, GH / 32), tb32>>>(poW, wT, GH, ED, 0, 0);
    gemm(xr, wT, tb, NNODE, ED, GH);
    kBiasAdd<<<(NNODE * ED) / 256, 256>>>(tb, pob, ge, ED, NNODE * ED);

    // query tower (reuse Wh as rounded-input scratch; free between layers)
    kRound<<<(BB * ED) / 1024, 256>>>((const float4*)query, (float4*)Wh);
    kTransRound<<<dim3(ED / 32, ED / 32), tb32>>>(qW1, wT, ED, ED, 0, 0);
    gemm(Wh, wT, tmp1, BB, ED, ED);
    kLnGelu<<<BB, 256>>>(tmp1, qb1, qg, qbt, tmp2);
    kTransRound<<<dim3(ED / 32, ED / 32), tb32>>>(qW2, wT, ED, ED, 0, 0);
    gemm(tmp2, wT, tmp1, BB, ED, ED);
    kBiasL2<<<BB, 256>>>(tmp1, qb2, q);

    // doc tower
    kRound<<<(BB * ED) / 1024, 256>>>((const float4*)docs, (float4*)Wh);
    kTransRound<<<dim3(ED / 32, ED / 32), tb32>>>(dW1, wT, ED, ED, 0, 0);
    gemm(Wh, wT, tmp1, BB, ED, ED);
    kLnGelu<<<BB, 256>>>(tmp1, db1, dg, dbt, tmp2);
    kTransRound<<<dim3(ED / 32, ED / 32), tb32>>>(dW2, wT, ED, ED, 0, 0);
    gemm(tmp2, wT, tmp1, BB, ED, ED);
    kBiasL2<<<BB, 256>>>(tmp1, db2, p);

    // similarities + InfoNCE
    gemm(q, p, neg, BB, BB, ED);
    kLse<<<BB, 256>>>(neg, rowv);
    kMeanRow<<<1, 256>>>(rowv, scal);

    // laplacian term
    kTransRound<<<dim3(ED / 32, NNODE / 32), tb32>>>(ge, geT, NNODE, ED, 0, 0);
    gemm(lapr, geT, tb, NNODE, ED, NNODE);
    kDotPart<<<256, 256>>>(ge, tb, part, NNODE * ED);
    kDotFinal<<<1, 256>>>(part, scal);

    kFinal<<<1, 32>>>(scal, (float*)d_out, out_size);
}